// round 11
// baseline (speedup 1.0000x reference)
#include <cuda_runtime.h>
#include <math.h>

#define BB 2
#define NN 262144
#define KK 9      // K+1 slots
#define DD 64
#define SS 64
#define PTS 512   // points per block (2 per thread)
#define BG_BOUND 1.0f
#define SCALE_F 0.125f

// ---------------------------------------------------------------------------
// Folded per-batch operands; computed on device, copied into __constant__.
// Warp-uniform indices in the main kernel -> LDCU; shared by both points of
// a thread via CSE, halving the constant-load instruction stream.
// ---------------------------------------------------------------------------
struct __align__(16) PreData {
    float M[BB][KK][DD];   // M = K @ Wq          (logit matrix)
    float P[BB][KK][DD];   // P = slots_full @ out_w^T
    float c[BB][KK];       // c = K @ Wq_b
    float ob[DD];          // out_b
    float ds;              // exp(density_scale)
};
__device__    PreData g_pre;
__constant__  PreData c_pre;

// ---------------------------------------------------------------------------
// Precompute: one block per (batch, slot) pair -> 18 blocks, 64 threads.
// ---------------------------------------------------------------------------
__global__ __launch_bounds__(64)
void precompute(const float* __restrict__ slots,
                const float* __restrict__ empty_slot,
                const float* __restrict__ Wq_w,
                const float* __restrict__ Wq_b,
                const float* __restrict__ Wk_w,
                const float* __restrict__ Wk_b,
                const float* __restrict__ out_w,
                const float* __restrict__ out_b,
                const float* __restrict__ dscale)
{
    __shared__ float sSlot[SS];
    __shared__ float sK[DD];

    const int b = blockIdx.x / KK;
    const int j = blockIdx.x % KK;
    const int d = threadIdx.x;

    sSlot[d] = (j == 0) ? empty_slot[d]
                        : slots[((size_t)b * (KK - 1) + (j - 1)) * SS + d];
    __syncthreads();

    const float4* wk4 = reinterpret_cast<const float4*>(Wk_w  + d * SS);
    const float4* ow4 = reinterpret_cast<const float4*>(out_w + d * SS);
    float kk = Wk_b[d];
    float pp = 0.f;
#pragma unroll
    for (int i = 0; i < SS / 4; i++) {
        const float4 wv = wk4[i];
        const float4 ov = ow4[i];
        const float s0 = sSlot[4 * i], s1 = sSlot[4 * i + 1];
        const float s2 = sSlot[4 * i + 2], s3 = sSlot[4 * i + 3];
        kk = fmaf(s0, wv.x, fmaf(s1, wv.y, fmaf(s2, wv.z, fmaf(s3, wv.w, kk))));
        pp = fmaf(s0, ov.x, fmaf(s1, ov.y, fmaf(s2, ov.z, fmaf(s3, ov.w, pp))));
    }
    sK[d] = kk;
    g_pre.P[b][j][d] = pp;

    if (blockIdx.x == 0) {
        g_pre.ob[d] = out_b[d];
        if (d == 0) g_pre.ds = __expf(dscale[0]);
    }
    __syncthreads();

    float m = 0.f;
#pragma unroll 8
    for (int dd = 0; dd < DD; dd++)
        m = fmaf(sK[dd], Wq_w[dd * DD + d], m);
    g_pre.M[b][j][d] = m;

    if (d == 0) {
        float cc = 0.f;
        for (int dd = 0; dd < DD; dd++)
            cc = fmaf(Wq_b[dd], sK[dd], cc);
        g_pre.c[b][j] = cc;
    }
}

// ---------------------------------------------------------------------------
// Main kernel: 256 threads, 512 points per block (thread owns tid, tid+256).
// Both points share every LDCU of M/P via CSE. Transpose tile planes have
// stride 514 f4 == 2 (mod 8): staging [q&3][q>>2], consume [ii][tid] and
// [ii][256+tid], and copy-out are all at the 4-phase .128 floor.
// ---------------------------------------------------------------------------
__global__ __launch_bounds__(256, 4)
void joint_decoder_main(const float* __restrict__ pf,
                        const float* __restrict__ coor,
                        float* __restrict__ xo,
                        float* __restrict__ wout,
                        float* __restrict__ sig)
{
    __shared__ float4 sT4[4][514];       // transpose tile for 512 points
    __shared__ float  sW[PTS * KK];      // staged w for coalesced stores

    const int tid = threadIdx.x;
    const int p0  = blockIdx.x * PTS;
    const int b   = blockIdx.x >> 9;     // 512 blocks per batch
    const int pA  = p0 + tid;
    const int pB  = pA + 256;

    const float4* pf4 = reinterpret_cast<const float4*>(pf + (size_t)p0 * DD);

    // ---- Phase 1: logits for both points, 4 tiles ----
    float accA[KK], accB[KK];
#pragma unroll
    for (int j = 0; j < KK; j++) { accA[j] = 0.f; accB[j] = 0.f; }

#pragma unroll
    for (int it = 0; it < 4; it++) {
        if (it) __syncthreads();                 // previous tile fully consumed
#pragma unroll
        for (int r = 0; r < 8; r++) {            // stage 2048 f4 coalesced
            const int q = r * 256 + tid;
            sT4[q & 3][q >> 2] = pf4[(q >> 2) * 16 + it * 4 + (q & 3)];
        }
        __syncthreads();
#pragma unroll
        for (int ii = 0; ii < 4; ii++) {
            const float4 xa = sT4[ii][tid];
            const float4 xb = sT4[ii][256 + tid];
            const int i4 = (it * 4 + ii) * 4;
#pragma unroll
            for (int j = 0; j < KK; j++) {
                const float m0 = c_pre.M[b][j][i4 + 0];
                const float m1 = c_pre.M[b][j][i4 + 1];
                const float m2 = c_pre.M[b][j][i4 + 2];
                const float m3 = c_pre.M[b][j][i4 + 3];
                accA[j] = fmaf(xa.x, m0, fmaf(xa.y, m1,
                          fmaf(xa.z, m2, fmaf(xa.w, m3, accA[j]))));
                accB[j] = fmaf(xb.x, m0, fmaf(xb.y, m1,
                          fmaf(xb.z, m2, fmaf(xb.w, m3, accB[j]))));
            }
        }
    }

    float logA[KK], logB[KK];
#pragma unroll
    for (int j = 0; j < KK; j++) {
        const float cj = c_pre.c[b][j];
        logA[j] = (accA[j] + cj) * SCALE_F;
        logB[j] = (accB[j] + cj) * SCALE_F;
    }

    // ---- force_bg mask: direct scalar LDG (lanes 12B apart -> ~3 lines) ----
    const float* cA = coor + (size_t)pA * 3;
    const float* cB = coor + (size_t)pB * 3;
    const bool inbA = (fabsf(cA[0]) <= BG_BOUND) && (fabsf(cA[1]) <= BG_BOUND) &&
                      (fabsf(cA[2]) <= BG_BOUND);
    const bool inbB = (fabsf(cB[0]) <= BG_BOUND) && (fabsf(cB[1]) <= BG_BOUND) &&
                      (fabsf(cB[2]) <= BG_BOUND);

    // ---- masked softmax + density (both points) ----
    float wA[KK], wB[KK];
    float sgA, sgB;
    {
        float mx = fmaxf(logA[0], logA[1]);
        if (inbA) {
#pragma unroll
            for (int j = 2; j < KK; j++) mx = fmaxf(mx, logA[j]);
        }
        wA[0] = __expf(logA[0] - mx);
        wA[1] = __expf(logA[1] - mx);
        float s = wA[0] + wA[1];
#pragma unroll
        for (int j = 2; j < KK; j++) {
            const float e = inbA ? __expf(logA[j] - mx) : 0.f;
            wA[j] = e; s += e;
        }
        const float inv = __frcp_rn(s);
        float sg = 0.f;
#pragma unroll
        for (int j = 0; j < KK; j++) wA[j] *= inv;
#pragma unroll
        for (int j = 1; j < KK; j++) sg = fmaf(fmaxf(logA[j], 0.f), wA[j], sg);
        sgA = sg;
    }
    {
        float mx = fmaxf(logB[0], logB[1]);
        if (inbB) {
#pragma unroll
            for (int j = 2; j < KK; j++) mx = fmaxf(mx, logB[j]);
        }
        wB[0] = __expf(logB[0] - mx);
        wB[1] = __expf(logB[1] - mx);
        float s = wB[0] + wB[1];
#pragma unroll
        for (int j = 2; j < KK; j++) {
            const float e = inbB ? __expf(logB[j] - mx) : 0.f;
            wB[j] = e; s += e;
        }
        const float inv = __frcp_rn(s);
        float sg = 0.f;
#pragma unroll
        for (int j = 0; j < KK; j++) wB[j] *= inv;
#pragma unroll
        for (int j = 1; j < KK; j++) sg = fmaf(fmaxf(logB[j], 0.f), wB[j], sg);
        sgB = sg;
    }

    sig[pA] = sgA * c_pre.ds;
    sig[pB] = sgB * c_pre.ds;
#pragma unroll
    for (int j = 0; j < KK; j++) {
        sW[tid * KK + j]         = wA[j];    // stride 9: conflict-free
        sW[(256 + tid) * KK + j] = wB[j];
    }

    // ---- Phase 2: xo for both points, 4 tiles ----
    float4* xo4 = reinterpret_cast<float4*>(xo + (size_t)p0 * DD);
#pragma unroll
    for (int it = 0; it < 4; it++) {
        __syncthreads();                 // prior copy-out / phase-1 LDS drained
#pragma unroll
        for (int ii = 0; ii < 4; ii++) {
            const int i4 = (it * 4 + ii) * 4;
            float4 oa, ob;
            oa.x = ob.x = c_pre.ob[i4 + 0];
            oa.y = ob.y = c_pre.ob[i4 + 1];
            oa.z = ob.z = c_pre.ob[i4 + 2];
            oa.w = ob.w = c_pre.ob[i4 + 3];
#pragma unroll
            for (int j = 0; j < KK; j++) {
                const float q0 = c_pre.P[b][j][i4 + 0];
                const float q1 = c_pre.P[b][j][i4 + 1];
                const float q2 = c_pre.P[b][j][i4 + 2];
                const float q3 = c_pre.P[b][j][i4 + 3];
                oa.x = fmaf(wA[j], q0, oa.x);  ob.x = fmaf(wB[j], q0, ob.x);
                oa.y = fmaf(wA[j], q1, oa.y);  ob.y = fmaf(wB[j], q1, ob.y);
                oa.z = fmaf(wA[j], q2, oa.z);  ob.z = fmaf(wB[j], q2, ob.z);
                oa.w = fmaf(wA[j], q3, oa.w);  ob.w = fmaf(wB[j], q3, ob.w);
            }
            sT4[ii][tid]       = oa;
            sT4[ii][256 + tid] = ob;
        }
        __syncthreads();
#pragma unroll
        for (int r = 0; r < 8; r++) {            // coalesced copy-out
            const int q = r * 256 + tid;
            xo4[(q >> 2) * 16 + it * 4 + (q & 3)] = sT4[q & 3][q >> 2];
        }
    }

    // ---- w out: float4-coalesced copy (ordered by phase-2 barriers) ----
    {
        const float4* sw4 = reinterpret_cast<const float4*>(sW);
        float4* wg4 = reinterpret_cast<float4*>(wout + (size_t)p0 * KK);
#pragma unroll
        for (int i = tid; i < (PTS * KK) / 4; i += 256)
            wg4[i] = sw4[i];
    }
}

// ---------------------------------------------------------------------------
// Launch
// ---------------------------------------------------------------------------
extern "C" void kernel_launch(void* const* d_in, const int* in_sizes, int n_in,
                              void* d_out, int out_size)
{
    const float* pf     = (const float*)d_in[0];   // point_feats [B,N,D]
    const float* slots  = (const float*)d_in[2];   // [B,K,S]
    const float* coor   = (const float*)d_in[3];   // [B,N,3]
    const float* empty  = (const float*)d_in[4];   // [1,1,S]
    const float* Wq_w   = (const float*)d_in[5];
    const float* Wq_b   = (const float*)d_in[6];
    const float* Wk_w   = (const float*)d_in[7];
    const float* Wk_b   = (const float*)d_in[8];
    const float* out_w  = (const float*)d_in[9];
    const float* out_b  = (const float*)d_in[10];
    const float* dscale = (const float*)d_in[11];

    float* out  = (float*)d_out;
    float* xo   = out;                              // [B,N,64]
    float* wout = out + (size_t)BB * NN * DD;       // [B,N,9]
    float* sig  = wout + (size_t)BB * NN * KK;      // [B,N]

    precompute<<<BB * KK, 64>>>(slots, empty, Wq_w, Wq_b, Wk_w, Wk_b,
                                out_w, out_b, dscale);

    void* g_pre_addr = nullptr;
    cudaGetSymbolAddress(&g_pre_addr, g_pre);
    cudaMemcpyToSymbolAsync(c_pre, g_pre_addr, sizeof(PreData), 0,
                            cudaMemcpyDeviceToDevice);

    joint_decoder_main<<<(BB * NN) / PTS, 256>>>(pf, coor, xo, wout, sig);
}

// round 12
// speedup vs baseline: 1.2819x; 1.2819x over previous
#include <cuda_runtime.h>
#include <math.h>

#define BB 2
#define NN 262144
#define KK 9      // K+1 slots
#define DD 64
#define SS 64
#define BG_BOUND 1.0f
#define SCALE_F 0.125f

// ---------------------------------------------------------------------------
// Folded per-batch operands; computed on device, copied into __constant__.
// Main kernel reads them as float4 with warp-uniform addresses -> LDCU.128
// (one uniform-port load per 4 FFMA operands).
// ---------------------------------------------------------------------------
struct __align__(16) PreData {
    float M[BB][KK][DD];   // M = K @ Wq          (logit matrix)
    float P[BB][KK][DD];   // P = slots_full @ out_w^T
    float c[BB][KK];       // c = K @ Wq_b
    float ob[DD];          // out_b
    float ds;              // exp(density_scale)
};
__device__    PreData g_pre;
__constant__  PreData c_pre;

// ---------------------------------------------------------------------------
// Precompute: one block per (batch, slot) pair -> 18 blocks, 64 threads.
// ---------------------------------------------------------------------------
__global__ __launch_bounds__(64)
void precompute(const float* __restrict__ slots,
                const float* __restrict__ empty_slot,
                const float* __restrict__ Wq_w,
                const float* __restrict__ Wq_b,
                const float* __restrict__ Wk_w,
                const float* __restrict__ Wk_b,
                const float* __restrict__ out_w,
                const float* __restrict__ out_b,
                const float* __restrict__ dscale)
{
    __shared__ float sSlot[SS];
    __shared__ float sK[DD];

    const int b = blockIdx.x / KK;
    const int j = blockIdx.x % KK;
    const int d = threadIdx.x;

    sSlot[d] = (j == 0) ? empty_slot[d]
                        : slots[((size_t)b * (KK - 1) + (j - 1)) * SS + d];
    __syncthreads();

    const float4* wk4 = reinterpret_cast<const float4*>(Wk_w  + d * SS);
    const float4* ow4 = reinterpret_cast<const float4*>(out_w + d * SS);
    float kk = Wk_b[d];
    float pp = 0.f;
#pragma unroll
    for (int i = 0; i < SS / 4; i++) {
        const float4 wv = wk4[i];
        const float4 ov = ow4[i];
        const float s0 = sSlot[4 * i], s1 = sSlot[4 * i + 1];
        const float s2 = sSlot[4 * i + 2], s3 = sSlot[4 * i + 3];
        kk = fmaf(s0, wv.x, fmaf(s1, wv.y, fmaf(s2, wv.z, fmaf(s3, wv.w, kk))));
        pp = fmaf(s0, ov.x, fmaf(s1, ov.y, fmaf(s2, ov.z, fmaf(s3, ov.w, pp))));
    }
    sK[d] = kk;
    g_pre.P[b][j][d] = pp;

    if (blockIdx.x == 0) {
        g_pre.ob[d] = out_b[d];
        if (d == 0) g_pre.ds = __expf(dscale[0]);
    }
    __syncthreads();

    float m = 0.f;
#pragma unroll 8
    for (int dd = 0; dd < DD; dd++)
        m = fmaf(sK[dd], Wq_w[dd * DD + d], m);
    g_pre.M[b][j][d] = m;

    if (d == 0) {
        float cc = 0.f;
        for (int dd = 0; dd < DD; dd++)
            cc = fmaf(Wq_b[dd], sK[dd], cc);
        g_pre.c[b][j] = cc;
    }
}

// ---------------------------------------------------------------------------
// Main kernel: 256 threads / 256 points per block (R8 structure).
// Conflict-free transpose tile sT4[4][258]; all constant operands fetched
// as float4 (LDCU.128) to quarter the uniform-load instruction stream.
// ---------------------------------------------------------------------------
__global__ __launch_bounds__(256)
void joint_decoder_main(const float* __restrict__ pf,
                        const float* __restrict__ coor,
                        float* __restrict__ xo,
                        float* __restrict__ wout,
                        float* __restrict__ sig)
{
    __shared__ float4 sT4[4][258];       // conflict-free transpose tile
    __shared__ float  sW[256 * KK];      // staged w for coalesced stores
    __shared__ float4 sCoor4[192];       // 256 pts * 3 floats

    const int tid = threadIdx.x;
    const int p0  = blockIdx.x * 256;
    const int b   = blockIdx.x >> 10;    // 1024 blocks per batch
    const int p   = p0 + tid;

    if (tid < 192)
        sCoor4[tid] = reinterpret_cast<const float4*>(coor + (size_t)p0 * 3)[tid];

    const float4* pf4 = reinterpret_cast<const float4*>(pf + (size_t)p0 * DD);

    // ---- Phase 1: logits via 4 transposed input tiles ----
    float acc[KK];
#pragma unroll
    for (int j = 0; j < KK; j++) acc[j] = 0.f;

#pragma unroll
    for (int it = 0; it < 4; it++) {
        if (it) __syncthreads();                 // previous tile fully consumed
#pragma unroll
        for (int r = 0; r < 4; r++) {
            const int q = r * 256 + tid;
            sT4[q & 3][q >> 2] = pf4[(q >> 2) * 16 + it * 4 + (q & 3)];
        }
        __syncthreads();
#pragma unroll
        for (int ii = 0; ii < 4; ii++) {
            const float4 x = sT4[ii][tid];
            const int i4 = (it * 4 + ii) * 4;
#pragma unroll
            for (int j = 0; j < KK; j++) {
                const float4 m = *reinterpret_cast<const float4*>(
                                     &c_pre.M[b][j][i4]);        // LDCU.128
                acc[j] = fmaf(x.x, m.x,
                         fmaf(x.y, m.y,
                         fmaf(x.z, m.z,
                         fmaf(x.w, m.w, acc[j]))));
            }
        }
    }
    __syncthreads();                             // sT4 free for output phase

    float logit[KK];
#pragma unroll
    for (int j = 0; j < KK; j++)
        logit[j] = (acc[j] + c_pre.c[b][j]) * SCALE_F;

    // ---- force_bg mask (coor from shared, stride-3 conflict-free) ----
    const float* cp = reinterpret_cast<const float*>(sCoor4) + tid * 3;
    const bool inb = (fabsf(cp[0]) <= BG_BOUND) && (fabsf(cp[1]) <= BG_BOUND) &&
                     (fabsf(cp[2]) <= BG_BOUND);

    // ---- masked softmax ----
    float mx = fmaxf(logit[0], logit[1]);
    if (inb) {
#pragma unroll
        for (int j = 2; j < KK; j++) mx = fmaxf(mx, logit[j]);
    }
    float w[KK];
    w[0] = __expf(logit[0] - mx);
    w[1] = __expf(logit[1] - mx);
    float s = w[0] + w[1];
#pragma unroll
    for (int j = 2; j < KK; j++) {
        const float e = inb ? __expf(logit[j] - mx) : 0.f;
        w[j] = e;
        s += e;
    }
    const float inv = __frcp_rn(s);
#pragma unroll
    for (int j = 0; j < KK; j++) w[j] *= inv;

    // ---- density + scalar outputs ----
    float sg = 0.f;
#pragma unroll
    for (int j = 1; j < KK; j++) sg = fmaf(fmaxf(logit[j], 0.f), w[j], sg);
    sig[p] = sg * c_pre.ds;

#pragma unroll
    for (int j = 0; j < KK; j++) sW[tid * KK + j] = w[j];   // stride 9: no conflicts

    // ---- Phase 2: xo via 4 transposed output tiles ----
    float4* xo4 = reinterpret_cast<float4*>(xo + (size_t)p0 * DD);
#pragma unroll
    for (int it = 0; it < 4; it++) {
        if (it) __syncthreads();                 // previous tile fully drained
#pragma unroll
        for (int ii = 0; ii < 4; ii++) {
            const int i4 = (it * 4 + ii) * 4;
            float4 o = *reinterpret_cast<const float4*>(&c_pre.ob[i4]); // LDCU.128
#pragma unroll
            for (int j = 0; j < KK; j++) {
                const float4 q = *reinterpret_cast<const float4*>(
                                     &c_pre.P[b][j][i4]);        // LDCU.128
                o.x = fmaf(w[j], q.x, o.x);
                o.y = fmaf(w[j], q.y, o.y);
                o.z = fmaf(w[j], q.z, o.z);
                o.w = fmaf(w[j], q.w, o.w);
            }
            sT4[ii][tid] = o;
        }
        __syncthreads();
#pragma unroll
        for (int r = 0; r < 4; r++) {
            const int q = r * 256 + tid;
            xo4[(q >> 2) * 16 + it * 4 + (q & 3)] = sT4[q & 3][q >> 2];
        }
    }

    // ---- w out: float4-coalesced copy (ordered by the phase-2 barriers) ----
    {
        const float4* sw4 = reinterpret_cast<const float4*>(sW);
        float4* wg4 = reinterpret_cast<float4*>(wout + (size_t)p0 * KK);
        wg4[tid]       = sw4[tid];
        wg4[tid + 256] = sw4[tid + 256];
        if (tid < 64) wg4[tid + 512] = sw4[tid + 512];
    }
}

// ---------------------------------------------------------------------------
// Launch
// ---------------------------------------------------------------------------
extern "C" void kernel_launch(void* const* d_in, const int* in_sizes, int n_in,
                              void* d_out, int out_size)
{
    const float* pf     = (const float*)d_in[0];   // point_feats [B,N,D]
    const float* slots  = (const float*)d_in[2];   // [B,K,S]
    const float* coor   = (const float*)d_in[3];   // [B,N,3]
    const float* empty  = (const float*)d_in[4];   // [1,1,S]
    const float* Wq_w   = (const float*)d_in[5];
    const float* Wq_b   = (const float*)d_in[6];
    const float* Wk_w   = (const float*)d_in[7];
    const float* Wk_b   = (const float*)d_in[8];
    const float* out_w  = (const float*)d_in[9];
    const float* out_b  = (const float*)d_in[10];
    const float* dscale = (const float*)d_in[11];

    float* out  = (float*)d_out;
    float* xo   = out;                              // [B,N,64]
    float* wout = out + (size_t)BB * NN * DD;       // [B,N,9]
    float* sig  = wout + (size_t)BB * NN * KK;      // [B,N]

    precompute<<<BB * KK, 64>>>(slots, empty, Wq_w, Wq_b, Wk_w, Wk_b,
                                out_w, out_b, dscale);

    void* g_pre_addr = nullptr;
    cudaGetSymbolAddress(&g_pre_addr, g_pre);
    cudaMemcpyToSymbolAsync(c_pre, g_pre_addr, sizeof(PreData), 0,
                            cudaMemcpyDeviceToDevice);

    joint_decoder_main<<<(BB * NN) / 256, 256>>>(pf, coor, xo, wout, sig);
}